// round 1
// baseline (speedup 1.0000x reference)
#include <cuda_runtime.h>

// MMDLayer: out[t,s] = (1 - ||x_t - C[511+t-s]||^2 / 128)^3
// where C[k] = init[511-k] (k<512) else x[k-512].
// Computed as banded GEMM: dot(x_t, C_k) for k in [t, t+511], plus row norms.

#define T_LEN 2048
#define S_LEN 512
#define D_LEN 128
#define BT 64
#define BK 64
#define PADW 132          // smem row stride in floats (528B, 16B aligned, conflict-free)
#define NKT 9             // k-tiles per t-block: covers k in [t0, t0+575]

__global__ __launch_bounds__(128, 2)
void mmd_band_kernel(const float* __restrict__ x,
                     const float* __restrict__ init,
                     float* __restrict__ out)
{
    extern __shared__ float sm[];
    float* As  = sm;                    // [BT][PADW] : x rows t0..t0+63
    float* Bs  = sm + BT * PADW;        // [BK][PADW] : C rows k0..k0+63
    float* nrm = sm + 2 * BT * PADW;    // [128] : [0..63] A-row norms, [64..127] B-row norms

    const int t0 = blockIdx.y * BT;
    const int k0 = t0 + blockIdx.x * BK;
    const int tid = threadIdx.x;

    // ---- Load A tile (coalesced float4, conflict-free STS) ----
    #pragma unroll
    for (int idx = tid; idx < BT * 32; idx += 128) {
        int r = idx >> 5;
        int c = idx & 31;
        float4 v = reinterpret_cast<const float4*>(x + (size_t)(t0 + r) * D_LEN)[c];
        reinterpret_cast<float4*>(As + r * PADW)[c] = v;
    }
    // ---- Load B tile: virtual C rows ----
    #pragma unroll
    for (int idx = tid; idx < BK * 32; idx += 128) {
        int r = idx >> 5;
        int c = idx & 31;
        int k = k0 + r;
        const float* src = (k < S_LEN) ? (init + (size_t)(S_LEN - 1 - k) * D_LEN)
                                       : (x    + (size_t)(k - S_LEN) * D_LEN);
        float4 v = reinterpret_cast<const float4*>(src)[c];
        reinterpret_cast<float4*>(Bs + r * PADW)[c] = v;
    }
    __syncthreads();

    // ---- Per-row squared norms from smem (thread r -> row r) ----
    {
        const float* row = (tid < 64) ? (As + tid * PADW) : (Bs + (tid - 64) * PADW);
        float acc = 0.f;
        #pragma unroll
        for (int c = 0; c < 32; c++) {
            float4 v = reinterpret_cast<const float4*>(row)[c];
            acc += v.x * v.x;
            acc += v.y * v.y;
            acc += v.z * v.z;
            acc += v.w * v.w;
        }
        nrm[tid] = acc;
    }
    __syncthreads();

    const int tx = tid & 15;   // k-lane (stride-16 micro in k)
    const int ty = tid >> 4;   // t-lane (stride-8 micro in t)

    float acc[8][4];
    #pragma unroll
    for (int i = 0; i < 8; i++)
        #pragma unroll
        for (int j = 0; j < 4; j++)
            acc[i][j] = 0.f;

    // ---- Main loop: dot products over D, float4 chunks ----
    #pragma unroll 2
    for (int c = 0; c < 32; c++) {
        float4 a[8], b[4];
        #pragma unroll
        for (int i = 0; i < 8; i++)
            a[i] = *reinterpret_cast<const float4*>(As + (ty + 8 * i) * PADW + 4 * c);
        #pragma unroll
        for (int j = 0; j < 4; j++)
            b[j] = *reinterpret_cast<const float4*>(Bs + (tx + 16 * j) * PADW + 4 * c);
        #pragma unroll
        for (int i = 0; i < 8; i++) {
            #pragma unroll
            for (int j = 0; j < 4; j++) {
                acc[i][j] += a[i].x * b[j].x;
                acc[i][j] += a[i].y * b[j].y;
                acc[i][j] += a[i].z * b[j].z;
                acc[i][j] += a[i].w * b[j].w;
            }
        }
    }

    // ---- Epilogue: d2 = nA + nB - 2*dot; out = (1 - d2/128)^3 ----
    #pragma unroll
    for (int i = 0; i < 8; i++) {
        const int rt = ty + 8 * i;          // row within A tile
        const int t  = t0 + rt;
        const float nA = nrm[rt];
        #pragma unroll
        for (int j = 0; j < 4; j++) {
            const int rk = tx + 16 * j;     // row within B tile
            const int k  = k0 + rk;
            const int s  = 511 + t - k;
            if (s >= 0 && s < S_LEN) {
                float d2 = nA + nrm[64 + rk] - 2.0f * acc[i][j];
                float u  = 1.0f - d2 * (1.0f / 128.0f);
                out[(size_t)t * S_LEN + s] = u * u * u;
            }
        }
    }
}

extern "C" void kernel_launch(void* const* d_in, const int* in_sizes, int n_in,
                              void* d_out, int out_size)
{
    const float* x    = (const float*)d_in[0];   // (1, 2048, 1, 128) fp32
    const float* init = (const float*)d_in[1];   // (512, 128) fp32
    float* out = (float*)d_out;                  // (1, 2048, 512) fp32

    const int smem_bytes = (2 * BT * PADW + 128) * (int)sizeof(float); // 68096 B
    cudaFuncSetAttribute(mmd_band_kernel,
                         cudaFuncAttributeMaxDynamicSharedMemorySize, smem_bytes);

    dim3 grid(NKT, T_LEN / BT);   // (9, 32) = 288 blocks -> single wave on 148 SMs
    mmd_band_kernel<<<grid, 128, smem_bytes>>>(x, init, out);
}